// round 9
// baseline (speedup 1.0000x reference)
#include <cuda_runtime.h>
#include <cuda_bf16.h>
#include <math.h>
#include <stdint.h>

#define BATCH 16384
#define HDIM  512

typedef __nv_bfloat16 bf16;

// ================= portable PTX helpers (sm_80+ ISA only) =================
__device__ __forceinline__ uint32_t smem_u32(const void* p) {
    uint32_t a;
    asm("{ .reg .u64 t; cvta.to.shared.u64 t, %1; cvt.u32.u64 %0, t; }" : "=r"(a) : "l"(p));
    return a;
}
#define CP_ASYNC16(dst, src) \
    asm volatile("cp.async.cg.shared.global [%0], [%1], 16;" :: "r"(dst), "l"(src) : "memory")
#define CP_COMMIT() asm volatile("cp.async.commit_group;" ::: "memory")
#define CP_WAIT(n)  asm volatile("cp.async.wait_group %0;" :: "n"(n) : "memory")
#define LDMATRIX_X4(r0, r1, r2, r3, addr) \
    asm volatile("ldmatrix.sync.aligned.m8n8.x4.shared.b16 {%0,%1,%2,%3}, [%4];" \
        : "=r"(r0), "=r"(r1), "=r"(r2), "=r"(r3) : "r"(addr))
#define MMA16816(c0, c1, c2, c3, a0, a1, a2, a3, b0, b1) \
    asm volatile("mma.sync.aligned.m16n8k16.row.col.f32.bf16.bf16.f32 " \
        "{%0,%1,%2,%3}, {%4,%5,%6,%7}, {%8,%9}, {%0,%1,%2,%3};" \
        : "+f"(c0), "+f"(c1), "+f"(c2), "+f"(c3) \
        : "r"(a0), "r"(a1), "r"(a2), "r"(a3), "r"(b0), "r"(b1))

__device__ __forceinline__ uint32_t sw128(uint32_t off) { return off ^ ((off >> 3) & 0x70); }

// ================= scratch (static __device__) =================
__device__ float d_A[(size_t)BATCH * 1536];
__device__ float d_x[(size_t)BATCH * 512];
__device__ float d_y[(size_t)BATCH * 512];
__device__ float d_gen[2 * (size_t)BATCH * 512];
__device__ float d_cAll[2 * 1536];
__device__ float d_prior[1024];

__device__ bf16 d_imgH[(size_t)BATCH * 512],  d_imgL[(size_t)BATCH * 512];
__device__ bf16 d_textH[(size_t)BATCH * 512], d_textL[(size_t)BATCH * 512];
__device__ bf16 d_xH[(size_t)BATCH * 512],    d_xL[(size_t)BATCH * 512];
__device__ bf16 d_hH[(size_t)BATCH * 2048],   d_hL[(size_t)BATCH * 2048];
__device__ bf16 d_wavH[6 * 512 * 512],        d_wavL[6 * 512 * 512];
__device__ bf16 d_ipwH[2 * 512 * 512],        d_ipwL[2 * 512 * 512];
__device__ bf16 d_opwH[2 * 512 * 512],        d_opwL[2 * 512 * 512];
__device__ bf16 d_f1wH[(size_t)6 * 2048 * 512], d_f1wL[(size_t)6 * 2048 * 512];
__device__ bf16 d_f2wH[(size_t)6 * 2048 * 512], d_f2wL[(size_t)6 * 2048 * 512];

__device__ __forceinline__ float gelu_exact(float x) {
    return 0.5f * x * (1.0f + erff(x * 0.70710678118654752440f));
}
__device__ __forceinline__ void split_bf16(float v, unsigned short& h, unsigned short& l) {
    __nv_bfloat16 hb = __float2bfloat16_rn(v);
    float hf = __bfloat162float(hb);
    __nv_bfloat16 lb = __float2bfloat16_rn(v - hf);
    h = __bfloat16_as_ushort(hb);
    l = __bfloat16_as_ushort(lb);
}

// ================= mma.sync bf16 GEMM =================
// C[M,N] = epi(A[M,K] @ W[N,K]^T + bias); fp32 via bf16 hi/lo 3-term split (K' = 3K).
// CTA tile 256x128, BK=64 (128B rows, SW128). 8 warps in 4(m) x 2(n), warp tile
// 64x64 -> 32 MMA per 8 LDSM per k16 (2x the math density of 64x32 tiles).
// 2-stage cp.async double buffer (one group in flight), fused epilogue.
enum { EPI_BIAS = 0, EPI_GELU = 1, EPI_ADD = 2, EPI_RESMIX = 3 };

#define STAGES 2
#define OP_A_BYTES 32768          // 256 rows x 128 bytes
#define OP_B_BYTES 16384          // 128 rows x 128 bytes
#define STAGE_BYTES (OP_A_BYTES + OP_B_BYTES)
#define MM_SMEM (STAGES * STAGE_BYTES)

template <int EPI>
__global__ __launch_bounds__(256) void mm_gemm(
    const bf16* __restrict__ Ahi, const bf16* __restrict__ Alo,
    const bf16* __restrict__ Bhi, const bf16* __restrict__ Blo,
    const float* __restrict__ bias, const float* __restrict__ aux,
    const float* __restrict__ rwp, int rwi,
    float* __restrict__ Cf, bf16* __restrict__ Chi, bf16* __restrict__ Clo,
    int M, int N, int K)
{
    extern __shared__ char smem[];
    const uint32_t sb = smem_u32(smem);
    const int tid = threadIdx.x;
    const int wid = tid >> 5, lane = tid & 31;
    const int warp_m = wid & 3;           // 0..3 -> 64-row quarter of 256
    const int warp_n = wid >> 2;          // 0..1 -> 64-col half of 128
    const int bm = blockIdx.y * 256, bn = blockIdx.x * 128;
    const int nk = K >> 6;
    const int nIter = 3 * nk;

    const size_t rowPitch = (size_t)K * 2;

    auto load_tile = [&](int s, int kt) {
        const bf16 *As, *Bs; int kk;
        if (kt < nk)           { As = Ahi; Bs = Bhi; kk = kt; }
        else if (kt < 2 * nk)  { As = Ahi; Bs = Blo; kk = kt - nk; }
        else                   { As = Alo; Bs = Bhi; kk = kt - 2 * nk; }
        const char* gA = (const char*)(As + (size_t)bm * K) + (size_t)kk * 128;
        const char* gB = (const char*)(Bs + (size_t)bn * K) + (size_t)kk * 128;
        uint32_t sA = sb + s * STAGE_BYTES;
        uint32_t sB = sA + OP_A_BYTES;
#pragma unroll
        for (int i = 0; i < 8; i++) {      // A: 256 rows
            int id = i * 256 + tid;
            int row = id >> 3, u = id & 7;
            uint32_t so = sw128((uint32_t)(row * 128 + u * 16));
            CP_ASYNC16(sA + so, gA + (size_t)row * rowPitch + u * 16);
        }
#pragma unroll
        for (int i = 0; i < 4; i++) {      // B: 128 rows
            int id = i * 256 + tid;
            int row = id >> 3, u = id & 7;
            uint32_t so = sw128((uint32_t)(row * 128 + u * 16));
            CP_ASYNC16(sB + so, gB + (size_t)row * rowPitch + u * 16);
        }
    };

    float acc[4][8][4];
#pragma unroll
    for (int i = 0; i < 4; i++)
#pragma unroll
        for (int j = 0; j < 8; j++)
#pragma unroll
            for (int e = 0; e < 4; e++) acc[i][j][e] = 0.0f;

    const int g = lane >> 3, lr = lane & 7;
    // A ldmatrix lane->addr pieces: rows m0-7/m8-15, kbytes 0/16
    const int arow = warp_m * 64 + (g & 1) * 8 + lr;
    const int akb  = (g >> 1) * 16;
    // B ldmatrix lane->addr pieces: rows n0-7/n8-15, kbytes 0/16
    const int brow = warp_n * 64 + (g >> 1) * 8 + lr;
    const int bkb  = (g & 1) * 16;

    load_tile(0, 0); CP_COMMIT();

    for (int kt = 0; kt < nIter; kt++) {
        if (kt + 1 < nIter) {
            load_tile((kt + 1) & 1, kt + 1);
            CP_COMMIT();
            CP_WAIT(1);      // tile kt complete; kt+1 still in flight
        } else {
            CP_WAIT(0);
        }
        __syncthreads();

        uint32_t sA = sb + (kt & 1) * STAGE_BYTES;
        uint32_t sB = sA + OP_A_BYTES;
#pragma unroll
        for (int ki = 0; ki < 4; ki++) {
            uint32_t a[4][4];
#pragma unroll
            for (int mt = 0; mt < 4; mt++) {
                uint32_t addr = sA + sw128((uint32_t)((arow + mt * 16) * 128 + ki * 32 + akb));
                LDMATRIX_X4(a[mt][0], a[mt][1], a[mt][2], a[mt][3], addr);
            }
            uint32_t b[8][2];
#pragma unroll
            for (int p = 0; p < 4; p++) {
                uint32_t addr = sB + sw128((uint32_t)((brow + p * 16) * 128 + ki * 32 + bkb));
                uint32_t r0, r1, r2, r3;
                LDMATRIX_X4(r0, r1, r2, r3, addr);
                b[2 * p][0] = r0;     b[2 * p][1] = r1;
                b[2 * p + 1][0] = r2; b[2 * p + 1][1] = r3;
            }
#pragma unroll
            for (int mt = 0; mt < 4; mt++)
#pragma unroll
                for (int nt = 0; nt < 8; nt++)
                    MMA16816(acc[mt][nt][0], acc[mt][nt][1], acc[mt][nt][2], acc[mt][nt][3],
                             a[mt][0], a[mt][1], a[mt][2], a[mt][3],
                             b[nt][0], b[nt][1]);
        }
        __syncthreads();     // buffer kt&1 free for iteration kt+1's prefetch
    }

    // ---- epilogue straight from fragments ----
    float rwv = 0.0f, rwc = 0.0f;
    if (EPI == EPI_RESMIX) { rwv = rwp[rwi]; rwc = 1.0f - rwv; }
    const int qr = lane >> 2, qc = (lane & 3) * 2;

#pragma unroll
    for (int mt = 0; mt < 4; mt++) {
#pragma unroll
        for (int nt = 0; nt < 8; nt++) {
            int n = bn + warp_n * 64 + nt * 8 + qc;
            float2 b2 = *(const float2*)(bias + n);
#pragma unroll
            for (int h = 0; h < 2; h++) {
                int m = bm + warp_m * 64 + mt * 16 + qr + h * 8;
                float v0 = acc[mt][nt][2 * h + 0] + b2.x;
                float v1 = acc[mt][nt][2 * h + 1] + b2.y;
                size_t gr = (size_t)m * N + n;
                if (EPI == EPI_GELU) { v0 = gelu_exact(v0); v1 = gelu_exact(v1); }
                if (EPI == EPI_ADD) {
                    float2 a2 = *(const float2*)(aux + gr);
                    v0 += a2.x; v1 += a2.y;
                }
                if (EPI == EPI_RESMIX) {
                    float2 a2 = *(const float2*)(aux + gr);
                    v0 = rwv * a2.x + rwc * v0;
                    v1 = rwv * a2.y + rwc * v1;
                }
                if (Cf) *(float2*)(Cf + gr) = make_float2(v0, v1);
                if (Chi) {
                    ushort2 hh, ll;
                    split_bf16(v0, hh.x, ll.x);
                    split_bf16(v1, hh.y, ll.y);
                    *(ushort2*)(Chi + gr) = hh;
                    *(ushort2*)(Clo + gr) = ll;
                }
            }
        }
    }
}

// ================= LayerNorm (fp32 out + bf16 hi/lo planes) =================
__global__ void ln_kernel(const float* __restrict__ x, const float* __restrict__ add,
                          int addStride,
                          const float* __restrict__ gg, const float* __restrict__ bb,
                          float* __restrict__ out, bf16* __restrict__ outH, bf16* __restrict__ outL)
{
    __shared__ float red[4];
    int row = blockIdx.x;
    int t = threadIdx.x;

    float4 v = ((const float4*)(x + (size_t)row * 512))[t];
    if (add) {
        float4 a = ((const float4*)(add + (size_t)row * addStride))[t];
        v.x += a.x; v.y += a.y; v.z += a.z; v.w += a.w;
    }
    float s = v.x + v.y + v.z + v.w;
#pragma unroll
    for (int o = 16; o; o >>= 1) s += __shfl_xor_sync(0xffffffff, s, o);
    if ((t & 31) == 0) red[t >> 5] = s;
    __syncthreads();
    float mean = (red[0] + red[1] + red[2] + red[3]) * (1.0f / 512.0f);

    float dx0 = v.x - mean, dx1 = v.y - mean, dx2 = v.z - mean, dx3 = v.w - mean;
    float q = dx0 * dx0 + dx1 * dx1 + dx2 * dx2 + dx3 * dx3;
#pragma unroll
    for (int o = 16; o; o >>= 1) q += __shfl_xor_sync(0xffffffff, q, o);
    __syncthreads();
    if ((t & 31) == 0) red[t >> 5] = q;
    __syncthreads();
    float var = (red[0] + red[1] + red[2] + red[3]) * (1.0f / 512.0f);
    float inv = rsqrtf(var + 1e-5f);

    float4 gv = ((const float4*)gg)[t];
    float4 bv = ((const float4*)bb)[t];
    float4 o4;
    o4.x = dx0 * inv * gv.x + bv.x;
    o4.y = dx1 * inv * gv.y + bv.y;
    o4.z = dx2 * inv * gv.z + bv.z;
    o4.w = dx3 * inv * gv.w + bv.w;
    ((float4*)(out + (size_t)row * 512))[t] = o4;

    ushort4 h, l;
    split_bf16(o4.x, h.x, l.x); split_bf16(o4.y, h.y, l.y);
    split_bf16(o4.z, h.z, l.z); split_bf16(o4.w, h.w, l.w);
    *(ushort4*)(outH + (size_t)row * 512 + t * 4) = h;
    *(ushort4*)(outL + (size_t)row * 512 + t * 4) = l;
}

// ================= Wav prep: Wav[z] = ao_w[z] @ wv[z] -> bf16 planes =================
__global__ __launch_bounds__(256) void wav_kernel(const float* __restrict__ ao_w,
                                                  const float* __restrict__ qkv_w,
                                                  bf16* __restrict__ WavH, bf16* __restrict__ WavL)
{
    __shared__ float As[16][64];
    __shared__ float Bs[16][64];
    int z = blockIdx.z;
    const float* AO = ao_w + (size_t)z * 512 * 512;
    const float* WV = qkv_w + (size_t)z * 1536 * 512 + (size_t)1024 * 512;
    int tid = threadIdx.x, tx = tid & 15, ty = tid >> 4;
    int bm = blockIdx.y * 64, bn = blockIdx.x * 64;
    int ar = tid >> 2, akc = (tid & 3) * 4;
    int bkr = tid >> 4, bjc = (tid & 15) * 4;

    float acc[4][4];
#pragma unroll
    for (int i = 0; i < 4; i++)
#pragma unroll
        for (int j = 0; j < 4; j++) acc[i][j] = 0.0f;

    for (int kt = 0; kt < 512; kt += 16) {
        float4 a = *(const float4*)(AO + (size_t)(bm + ar) * 512 + kt + akc);
        float4 b = *(const float4*)(WV + (size_t)(kt + bkr) * 512 + bn + bjc);
        __syncthreads();
        As[akc + 0][ar] = a.x; As[akc + 1][ar] = a.y;
        As[akc + 2][ar] = a.z; As[akc + 3][ar] = a.w;
        *(float4*)&Bs[bkr][bjc] = b;
        __syncthreads();
#pragma unroll
        for (int kk = 0; kk < 16; kk++) {
            float av[4], bv[4];
            *(float4*)av = *(const float4*)&As[kk][ty * 4];
            *(float4*)bv = *(const float4*)&Bs[kk][tx * 4];
#pragma unroll
            for (int i = 0; i < 4; i++)
#pragma unroll
                for (int j = 0; j < 4; j++) acc[i][j] += av[i] * bv[j];
        }
    }
#pragma unroll
    for (int i = 0; i < 4; i++) {
        ushort4 h, l;
        split_bf16(acc[i][0], h.x, l.x); split_bf16(acc[i][1], h.y, l.y);
        split_bf16(acc[i][2], h.z, l.z); split_bf16(acc[i][3], h.w, l.w);
        size_t off = (size_t)z * 512 * 512 + (size_t)(bm + ty * 4 + i) * 512 + bn + tx * 4;
        *(ushort4*)(WavH + off) = h;
        *(ushort4*)(WavL + off) = l;
    }
}

// ================= folded bias =================
__global__ void cvec_kernel(const float* __restrict__ ao_w, const float* __restrict__ ao_b,
                            const float* __restrict__ qkv_b, float* __restrict__ cAll)
{
    int z = blockIdx.x;
    int r = threadIdx.x;
    const float* AO = ao_w + (size_t)z * 512 * 512 + (size_t)r * 512;
    const float* bv = qkv_b + (size_t)z * 1536 + 1024;
    float s = ao_b[z * 512 + r];
    for (int k = 0; k < 512; k++) s += AO[k] * bv[k];
    cAll[z * 512 + r] = s;
}

// ================= prior MLP =================
__global__ void prior_kernel(const float* __restrict__ w1, const float* __restrict__ b1,
                             const float* __restrict__ w2, const float* __restrict__ b2,
                             const float* __restrict__ emb, float* __restrict__ prior)
{
    __shared__ float e[512];
    __shared__ float h1[1024];
    int t = threadIdx.x;
    if (t < 512) e[t] = emb[t];
    __syncthreads();
    float s = b1[t];
    const float* wr = w1 + (size_t)t * 512;
    for (int k = 0; k < 512; k++) s += wr[k] * e[k];
    h1[t] = gelu_exact(s);
    __syncthreads();
    float s2 = b2[t];
    const float* wr2 = w2 + (size_t)t * 1024;
    for (int k = 0; k < 1024; k++) s2 += wr2[k] * h1[k];
    prior[t] = s2;
}

// ================= fp32 -> bf16 hi/lo split =================
__global__ void split_kernel(const float4* __restrict__ src, ushort4* __restrict__ hi,
                             ushort4* __restrict__ lo, int n4)
{
    int i = blockIdx.x * blockDim.x + threadIdx.x;
    if (i >= n4) return;
    float4 v = src[i];
    ushort4 h, l;
    split_bf16(v.x, h.x, l.x); split_bf16(v.y, h.y, l.y);
    split_bf16(v.z, h.z, l.z); split_bf16(v.w, h.w, l.w);
    hi[i] = h;
    lo[i] = l;
}

// ================= final combine =================
__global__ void combine_kernel(const float* __restrict__ img, const float* __restrict__ text,
                               const float* __restrict__ gen, const float* __restrict__ prior,
                               const int* __restrict__ mt, float* __restrict__ out)
{
    int idx = blockIdx.x * blockDim.x + threadIdx.x;
    int bi = idx >> 9;
    int h = idx & 511;
    int m = mt[bi];
    float ei = img[idx];
    if (m == 2) ei = gen[(size_t)BATCH * 512 + idx];
    if (m == 3) ei = prior[h];
    float et = text[idx];
    if (m == 1) et = gen[idx];
    if (m == 3) et = prior[512 + h];
    out[idx] = ei;
    out[(size_t)BATCH * 512 + idx] = et;
}

// ================= host-side pointer resolution + config =================
struct Scratch {
    float *A, *x, *y, *gen, *c, *prior;
    bf16 *imgH, *imgL, *textH, *textL, *xH, *xL, *hH, *hL;
    bf16 *wavH, *wavL, *ipwH, *ipwL, *opwH, *opwL, *f1wH, *f1wL, *f2wH, *f2wL;
};
static Scratch get_scratch() {
    static Scratch s;
    static bool init = false;
    if (!init) {
        cudaGetSymbolAddress((void**)&s.A, d_A);
        cudaGetSymbolAddress((void**)&s.x, d_x);
        cudaGetSymbolAddress((void**)&s.y, d_y);
        cudaGetSymbolAddress((void**)&s.gen, d_gen);
        cudaGetSymbolAddress((void**)&s.c, d_cAll);
        cudaGetSymbolAddress((void**)&s.prior, d_prior);
        cudaGetSymbolAddress((void**)&s.imgH, d_imgH);   cudaGetSymbolAddress((void**)&s.imgL, d_imgL);
        cudaGetSymbolAddress((void**)&s.textH, d_textH); cudaGetSymbolAddress((void**)&s.textL, d_textL);
        cudaGetSymbolAddress((void**)&s.xH, d_xH);       cudaGetSymbolAddress((void**)&s.xL, d_xL);
        cudaGetSymbolAddress((void**)&s.hH, d_hH);       cudaGetSymbolAddress((void**)&s.hL, d_hL);
        cudaGetSymbolAddress((void**)&s.wavH, d_wavH);   cudaGetSymbolAddress((void**)&s.wavL, d_wavL);
        cudaGetSymbolAddress((void**)&s.ipwH, d_ipwH);   cudaGetSymbolAddress((void**)&s.ipwL, d_ipwL);
        cudaGetSymbolAddress((void**)&s.opwH, d_opwH);   cudaGetSymbolAddress((void**)&s.opwL, d_opwL);
        cudaGetSymbolAddress((void**)&s.f1wH, d_f1wH);   cudaGetSymbolAddress((void**)&s.f1wL, d_f1wL);
        cudaGetSymbolAddress((void**)&s.f2wH, d_f2wH);   cudaGetSymbolAddress((void**)&s.f2wL, d_f2wL);
        cudaFuncSetAttribute(mm_gemm<EPI_BIAS>,   cudaFuncAttributeMaxDynamicSharedMemorySize, MM_SMEM);
        cudaFuncSetAttribute(mm_gemm<EPI_GELU>,   cudaFuncAttributeMaxDynamicSharedMemorySize, MM_SMEM);
        cudaFuncSetAttribute(mm_gemm<EPI_ADD>,    cudaFuncAttributeMaxDynamicSharedMemorySize, MM_SMEM);
        cudaFuncSetAttribute(mm_gemm<EPI_RESMIX>, cudaFuncAttributeMaxDynamicSharedMemorySize, MM_SMEM);
        init = true;
    }
    return s;
}

static void run_split(const float* src, bf16* hi, bf16* lo, size_t n) {
    int n4 = (int)(n / 4);
    split_kernel<<<(n4 + 255) / 256, 256>>>((const float4*)src, (ushort4*)hi, (ushort4*)lo, n4);
}

// ================= launch =================
extern "C" void kernel_launch(void* const* d_in, const int* in_sizes, int n_in,
                              void* d_out, int out_size)
{
    const float* img   = (const float*)d_in[0];
    const float* text  = (const float*)d_in[1];
    const float* ipw   = (const float*)d_in[2];
    const float* ipb   = (const float*)d_in[3];
    const float* qkv_w = (const float*)d_in[4];
    const float* qkv_b = (const float*)d_in[5];
    const float* ao_w  = (const float*)d_in[6];
    const float* ao_b  = (const float*)d_in[7];
    const float* ln1g  = (const float*)d_in[8];
    const float* ln1b  = (const float*)d_in[9];
    const float* ln2g  = (const float*)d_in[10];
    const float* ln2b  = (const float*)d_in[11];
    const float* f1w   = (const float*)d_in[12];
    const float* f1b   = (const float*)d_in[13];
    const float* f2w   = (const float*)d_in[14];
    const float* f2b   = (const float*)d_in[15];
    const float* opw   = (const float*)d_in[16];
    const float* opb   = (const float*)d_in[17];
    const float* rw    = (const float*)d_in[18];
    const float* pw1   = (const float*)d_in[19];
    const float* pb1   = (const float*)d_in[20];
    const float* pw2   = (const float*)d_in[21];
    const float* pb2   = (const float*)d_in[22];
    const float* pemb  = (const float*)d_in[23];
    const int*   mt    = (const int*)d_in[24];

    Scratch sc = get_scratch();
    const int M = BATCH;

    // ---- prep: splits, folded attention weights, folded bias, prior ----
    run_split(img,  sc.imgH,  sc.imgL,  (size_t)M * 512);
    run_split(text, sc.textH, sc.textL, (size_t)M * 512);
    run_split(ipw,  sc.ipwH,  sc.ipwL,  (size_t)2 * 512 * 512);
    run_split(opw,  sc.opwH,  sc.opwL,  (size_t)2 * 512 * 512);
    run_split(f1w,  sc.f1wH,  sc.f1wL,  (size_t)6 * 2048 * 512);
    run_split(f2w,  sc.f2wH,  sc.f2wL,  (size_t)6 * 2048 * 512);
    wav_kernel<<<dim3(8, 8, 6), 256>>>(ao_w, qkv_w, sc.wavH, sc.wavL);
    cvec_kernel<<<6, 512>>>(ao_w, ao_b, qkv_b, sc.c);
    prior_kernel<<<1, 1024>>>(pw1, pb1, pw2, pb2, pemb, sc.prior);

    for (int g = 0; g < 2; g++) {
        const float* tgt = (g == 0) ? text : img;
        const bf16* srcH = (g == 0) ? sc.imgH : sc.textH;
        const bf16* srcL = (g == 0) ? sc.imgL : sc.textL;
        const bf16* tgtH = (g == 0) ? sc.textH : sc.imgH;
        const bf16* tgtL = (g == 0) ? sc.textL : sc.imgL;
        size_t gw = (size_t)g;

        // x = src @ ipw^T + ipb
        mm_gemm<EPI_BIAS><<<dim3(4, M / 256), 256, MM_SMEM>>>(
            srcH, srcL, sc.ipwH + gw * 262144, sc.ipwL + gw * 262144,
            ipb + gw * 512, nullptr, nullptr, 0,
            sc.x, nullptr, nullptr, M, 512, 512);

        // A = tgt @ Wav^T + cAll (all 3 layers)
        mm_gemm<EPI_BIAS><<<dim3(12, M / 256), 256, MM_SMEM>>>(
            tgtH, tgtL, sc.wavH + gw * 786432, sc.wavL + gw * 786432,
            sc.c + gw * 1536, nullptr, nullptr, 0,
            sc.A, nullptr, nullptr, M, 1536, 512);

        for (int l = 0; l < 3; l++) {
            size_t zl = gw * 3 + l;
            ln_kernel<<<M, 128>>>(sc.x, sc.A + (size_t)l * 512, 1536,
                                  ln1g + zl * 512, ln1b + zl * 512, sc.x, sc.xH, sc.xL);
            mm_gemm<EPI_GELU><<<dim3(16, M / 256), 256, MM_SMEM>>>(
                sc.xH, sc.xL, sc.f1wH + zl * 1048576, sc.f1wL + zl * 1048576,
                f1b + zl * 2048, nullptr, nullptr, 0,
                nullptr, sc.hH, sc.hL, M, 2048, 512);
            mm_gemm<EPI_ADD><<<dim3(4, M / 256), 256, MM_SMEM>>>(
                sc.hH, sc.hL, sc.f2wH + zl * 1048576, sc.f2wL + zl * 1048576,
                f2b + zl * 512, sc.x, nullptr, 0,
                sc.y, nullptr, nullptr, M, 512, 2048);
            ln_kernel<<<M, 128>>>(sc.y, nullptr, 0,
                                  ln2g + zl * 512, ln2b + zl * 512, sc.x, sc.xH, sc.xL);
        }

        // gen = rw*tgt + (1-rw)*(x @ opw^T + opb)
        mm_gemm<EPI_RESMIX><<<dim3(4, M / 256), 256, MM_SMEM>>>(
            sc.xH, sc.xL, sc.opwH + gw * 262144, sc.opwL + gw * 262144,
            opb + gw * 512, tgt, rw, g,
            sc.gen + gw * (size_t)M * 512, nullptr, nullptr, M, 512, 512);
    }

    combine_kernel<<<(M * 512) / 256, 256>>>(img, text, sc.gen, sc.prior, mt, (float*)d_out);
}

// round 10
// speedup vs baseline: 1.1997x; 1.1997x over previous
#include <cuda_runtime.h>
#include <cuda_bf16.h>
#include <math.h>
#include <stdint.h>

#define BATCH 16384
#define HDIM  512

typedef __nv_bfloat16 bf16;

// ================= portable PTX helpers (sm_80+ ISA only) =================
__device__ __forceinline__ uint32_t smem_u32(const void* p) {
    uint32_t a;
    asm("{ .reg .u64 t; cvta.to.shared.u64 t, %1; cvt.u32.u64 %0, t; }" : "=r"(a) : "l"(p));
    return a;
}
#define CP_ASYNC16(dst, src) \
    asm volatile("cp.async.cg.shared.global [%0], [%1], 16;" :: "r"(dst), "l"(src) : "memory")
#define CP_COMMIT() asm volatile("cp.async.commit_group;" ::: "memory")
#define CP_WAIT(n)  asm volatile("cp.async.wait_group %0;" :: "n"(n) : "memory")
#define LDMATRIX_X4(r0, r1, r2, r3, addr) \
    asm volatile("ldmatrix.sync.aligned.m8n8.x4.shared.b16 {%0,%1,%2,%3}, [%4];" \
        : "=r"(r0), "=r"(r1), "=r"(r2), "=r"(r3) : "r"(addr))
#define MMA16816(c0, c1, c2, c3, a0, a1, a2, a3, b0, b1) \
    asm volatile("mma.sync.aligned.m16n8k16.row.col.f32.bf16.bf16.f32 " \
        "{%0,%1,%2,%3}, {%4,%5,%6,%7}, {%8,%9}, {%0,%1,%2,%3};" \
        : "+f"(c0), "+f"(c1), "+f"(c2), "+f"(c3) \
        : "r"(a0), "r"(a1), "r"(a2), "r"(a3), "r"(b0), "r"(b1))

__device__ __forceinline__ uint32_t sw128(uint32_t off) { return off ^ ((off >> 3) & 0x70); }

// ================= scratch (static __device__) =================
__device__ float d_A[(size_t)BATCH * 1536];
__device__ float d_x[(size_t)BATCH * 512];
__device__ float d_y[(size_t)BATCH * 512];
__device__ float d_gen[2 * (size_t)BATCH * 512];
__device__ float d_cAll[2 * 1536];
__device__ float d_prior[1024];

__device__ bf16 d_imgH[(size_t)BATCH * 512],  d_imgL[(size_t)BATCH * 512];
__device__ bf16 d_textH[(size_t)BATCH * 512], d_textL[(size_t)BATCH * 512];
__device__ bf16 d_xH[(size_t)BATCH * 512],    d_xL[(size_t)BATCH * 512];
__device__ bf16 d_hH[(size_t)BATCH * 2048],   d_hL[(size_t)BATCH * 2048];
__device__ bf16 d_wavH[6 * 512 * 512],        d_wavL[6 * 512 * 512];
__device__ bf16 d_ipwH[2 * 512 * 512],        d_ipwL[2 * 512 * 512];
__device__ bf16 d_opwH[2 * 512 * 512],        d_opwL[2 * 512 * 512];
__device__ bf16 d_f1wH[(size_t)6 * 2048 * 512], d_f1wL[(size_t)6 * 2048 * 512];
__device__ bf16 d_f2wH[(size_t)6 * 2048 * 512], d_f2wL[(size_t)6 * 2048 * 512];

__device__ __forceinline__ float gelu_exact(float x) {
    return 0.5f * x * (1.0f + erff(x * 0.70710678118654752440f));
}
__device__ __forceinline__ void split_bf16(float v, unsigned short& h, unsigned short& l) {
    __nv_bfloat16 hb = __float2bfloat16_rn(v);
    float hf = __bfloat162float(hb);
    __nv_bfloat16 lb = __float2bfloat16_rn(v - hf);
    h = __bfloat16_as_ushort(hb);
    l = __bfloat16_as_ushort(lb);
}

// ================= mma.sync bf16 GEMM =================
// C[M,N] = epi(A[M,K] @ W[N,K]^T + bias); fp32 via bf16 hi/lo 3-term split (K' = 3K).
// CTA tile 128x128, BK=64 bf16 (128B rows, SW128), 8 warps (64x32 each).
// 3-stage cp.async ring, TWO groups in flight, ONE __syncthreads per K-iter:
// the stage loaded at the end of iter kt (for kt+2) is the one consumed in
// iter kt-1, and every thread passed the top-of-kt barrier only after all
// threads finished iter kt-1 -> no write-after-read hazard with a single sync.
// __launch_bounds__(256,2) caps regs at 128 so 2 CTAs co-reside per SM.
enum { EPI_BIAS = 0, EPI_GELU = 1, EPI_ADD = 2, EPI_RESMIX = 3 };

#define STAGES 3
#define OP_BYTES 16384            // 128 rows x 128 bytes
#define STAGE_BYTES (2 * OP_BYTES)
#define MM_SMEM (STAGES * STAGE_BYTES)

template <int EPI>
__global__ __launch_bounds__(256, 2) void mm_gemm(
    const bf16* __restrict__ Ahi, const bf16* __restrict__ Alo,
    const bf16* __restrict__ Bhi, const bf16* __restrict__ Blo,
    const float* __restrict__ bias, const float* __restrict__ aux,
    const float* __restrict__ rwp, int rwi,
    float* __restrict__ Cf, bf16* __restrict__ Chi, bf16* __restrict__ Clo,
    int M, int N, int K)
{
    extern __shared__ char smem[];
    const uint32_t sb = smem_u32(smem);
    const int tid = threadIdx.x;
    const int wid = tid >> 5, lane = tid & 31;
    const int warp_m = wid >> 2;          // 0..1 -> 64-row half
    const int warp_n = wid & 3;           // 0..3 -> 32-col quarter
    const int bm = blockIdx.y * 128, bn = blockIdx.x * 128;
    const int nk = K >> 6;
    const int nIter = 3 * nk;

    const size_t rowPitch = (size_t)K * 2;

    auto load_tile = [&](int s, int kt) {
        const bf16 *As, *Bs; int kk;
        if (kt < nk)           { As = Ahi; Bs = Bhi; kk = kt; }
        else if (kt < 2 * nk)  { As = Ahi; Bs = Blo; kk = kt - nk; }
        else                   { As = Alo; Bs = Bhi; kk = kt - 2 * nk; }
        const char* gA = (const char*)(As + (size_t)bm * K) + (size_t)kk * 128;
        const char* gB = (const char*)(Bs + (size_t)bn * K) + (size_t)kk * 128;
        uint32_t sA = sb + s * STAGE_BYTES;
        uint32_t sB = sA + OP_BYTES;
#pragma unroll
        for (int i = 0; i < 4; i++) {
            int id = i * 256 + tid;
            int row = id >> 3, u = id & 7;
            uint32_t so = sw128((uint32_t)(row * 128 + u * 16));
            CP_ASYNC16(sA + so, gA + (size_t)row * rowPitch + u * 16);
            CP_ASYNC16(sB + so, gB + (size_t)row * rowPitch + u * 16);
        }
    };

    float acc[4][4][4];
#pragma unroll
    for (int i = 0; i < 4; i++)
#pragma unroll
        for (int j = 0; j < 4; j++)
#pragma unroll
            for (int e = 0; e < 4; e++) acc[i][j][e] = 0.0f;

    const int g = lane >> 3, lr = lane & 7;
    // A ldmatrix lane->addr pieces: rows m0-7/m8-15, kbytes 0/16
    const int arow = warp_m * 64 + (g & 1) * 8 + lr;
    const int akb  = (g >> 1) * 16;
    // B ldmatrix lane->addr pieces: rows n0-7/n8-15, kbytes 0/16
    const int brow = warp_n * 32 + (g >> 1) * 8 + lr;
    const int bkb  = (g & 1) * 16;

    load_tile(0, 0); CP_COMMIT();
    load_tile(1, 1); CP_COMMIT();

    for (int kt = 0; kt < nIter; kt++) {
        if (kt + 1 < nIter) { CP_WAIT(1); }   // tile kt done; kt+1 in flight
        else                { CP_WAIT(0); }   // last tile: drain
        __syncthreads();

        int s = kt;
        while (s >= STAGES) s -= STAGES;      // kt % 3 without div
        uint32_t sA = sb + s * STAGE_BYTES;
        uint32_t sB = sA + OP_BYTES;
#pragma unroll
        for (int ki = 0; ki < 4; ki++) {
            uint32_t a[4][4];
#pragma unroll
            for (int mt = 0; mt < 4; mt++) {
                uint32_t addr = sA + sw128((uint32_t)((arow + mt * 16) * 128 + ki * 32 + akb));
                LDMATRIX_X4(a[mt][0], a[mt][1], a[mt][2], a[mt][3], addr);
            }
            uint32_t b[4][2];
#pragma unroll
            for (int p = 0; p < 2; p++) {
                uint32_t addr = sB + sw128((uint32_t)((brow + p * 16) * 128 + ki * 32 + bkb));
                uint32_t r0, r1, r2, r3;
                LDMATRIX_X4(r0, r1, r2, r3, addr);
                b[2 * p][0] = r0;     b[2 * p][1] = r1;
                b[2 * p + 1][0] = r2; b[2 * p + 1][1] = r3;
            }
#pragma unroll
            for (int mt = 0; mt < 4; mt++)
#pragma unroll
                for (int nt = 0; nt < 4; nt++)
                    MMA16816(acc[mt][nt][0], acc[mt][nt][1], acc[mt][nt][2], acc[mt][nt][3],
                             a[mt][0], a[mt][1], a[mt][2], a[mt][3],
                             b[nt][0], b[nt][1]);
        }

        if (kt + 2 < nIter) {
            int s2 = kt + 2;
            while (s2 >= STAGES) s2 -= STAGES;
            load_tile(s2, kt + 2);            // stage consumed in iter kt-1: safe
            CP_COMMIT();
        }
    }

    // ---- epilogue straight from fragments ----
    float rwv = 0.0f, rwc = 0.0f;
    if (EPI == EPI_RESMIX) { rwv = rwp[rwi]; rwc = 1.0f - rwv; }
    const int qr = lane >> 2, qc = (lane & 3) * 2;

#pragma unroll
    for (int mt = 0; mt < 4; mt++) {
#pragma unroll
        for (int nt = 0; nt < 4; nt++) {
            int n = bn + warp_n * 32 + nt * 8 + qc;
            float2 b2 = *(const float2*)(bias + n);
#pragma unroll
            for (int h = 0; h < 2; h++) {
                int m = bm + warp_m * 64 + mt * 16 + qr + h * 8;
                float v0 = acc[mt][nt][2 * h + 0] + b2.x;
                float v1 = acc[mt][nt][2 * h + 1] + b2.y;
                size_t gr = (size_t)m * N + n;
                if (EPI == EPI_GELU) { v0 = gelu_exact(v0); v1 = gelu_exact(v1); }
                if (EPI == EPI_ADD) {
                    float2 a2 = *(const float2*)(aux + gr);
                    v0 += a2.x; v1 += a2.y;
                }
                if (EPI == EPI_RESMIX) {
                    float2 a2 = *(const float2*)(aux + gr);
                    v0 = rwv * a2.x + rwc * v0;
                    v1 = rwv * a2.y + rwc * v1;
                }
                if (Cf) *(float2*)(Cf + gr) = make_float2(v0, v1);
                if (Chi) {
                    ushort2 hh, ll;
                    split_bf16(v0, hh.x, ll.x);
                    split_bf16(v1, hh.y, ll.y);
                    *(ushort2*)(Chi + gr) = hh;
                    *(ushort2*)(Clo + gr) = ll;
                }
            }
        }
    }
}

// ================= LayerNorm (fp32 out + bf16 hi/lo planes) =================
__global__ void ln_kernel(const float* __restrict__ x, const float* __restrict__ add,
                          int addStride,
                          const float* __restrict__ gg, const float* __restrict__ bb,
                          float* __restrict__ out, bf16* __restrict__ outH, bf16* __restrict__ outL)
{
    __shared__ float red[4];
    int row = blockIdx.x;
    int t = threadIdx.x;

    float4 v = ((const float4*)(x + (size_t)row * 512))[t];
    if (add) {
        float4 a = ((const float4*)(add + (size_t)row * addStride))[t];
        v.x += a.x; v.y += a.y; v.z += a.z; v.w += a.w;
    }
    float s = v.x + v.y + v.z + v.w;
#pragma unroll
    for (int o = 16; o; o >>= 1) s += __shfl_xor_sync(0xffffffff, s, o);
    if ((t & 31) == 0) red[t >> 5] = s;
    __syncthreads();
    float mean = (red[0] + red[1] + red[2] + red[3]) * (1.0f / 512.0f);

    float dx0 = v.x - mean, dx1 = v.y - mean, dx2 = v.z - mean, dx3 = v.w - mean;
    float q = dx0 * dx0 + dx1 * dx1 + dx2 * dx2 + dx3 * dx3;
#pragma unroll
    for (int o = 16; o; o >>= 1) q += __shfl_xor_sync(0xffffffff, q, o);
    __syncthreads();
    if ((t & 31) == 0) red[t >> 5] = q;
    __syncthreads();
    float var = (red[0] + red[1] + red[2] + red[3]) * (1.0f / 512.0f);
    float inv = rsqrtf(var + 1e-5f);

    float4 gv = ((const float4*)gg)[t];
    float4 bv = ((const float4*)bb)[t];
    float4 o4;
    o4.x = dx0 * inv * gv.x + bv.x;
    o4.y = dx1 * inv * gv.y + bv.y;
    o4.z = dx2 * inv * gv.z + bv.z;
    o4.w = dx3 * inv * gv.w + bv.w;
    ((float4*)(out + (size_t)row * 512))[t] = o4;

    ushort4 h, l;
    split_bf16(o4.x, h.x, l.x); split_bf16(o4.y, h.y, l.y);
    split_bf16(o4.z, h.z, l.z); split_bf16(o4.w, h.w, l.w);
    *(ushort4*)(outH + (size_t)row * 512 + t * 4) = h;
    *(ushort4*)(outL + (size_t)row * 512 + t * 4) = l;
}

// ================= Wav prep: Wav[z] = ao_w[z] @ wv[z] -> bf16 planes =================
__global__ __launch_bounds__(256) void wav_kernel(const float* __restrict__ ao_w,
                                                  const float* __restrict__ qkv_w,
                                                  bf16* __restrict__ WavH, bf16* __restrict__ WavL)
{
    __shared__ float As[16][64];
    __shared__ float Bs[16][64];
    int z = blockIdx.z;
    const float* AO = ao_w + (size_t)z * 512 * 512;
    const float* WV = qkv_w + (size_t)z * 1536 * 512 + (size_t)1024 * 512;
    int tid = threadIdx.x, tx = tid & 15, ty = tid >> 4;
    int bm = blockIdx.y * 64, bn = blockIdx.x * 64;
    int ar = tid >> 2, akc = (tid & 3) * 4;
    int bkr = tid >> 4, bjc = (tid & 15) * 4;

    float acc[4][4];
#pragma unroll
    for (int i = 0; i < 4; i++)
#pragma unroll
        for (int j = 0; j < 4; j++) acc[i][j] = 0.0f;

    for (int kt = 0; kt < 512; kt += 16) {
        float4 a = *(const float4*)(AO + (size_t)(bm + ar) * 512 + kt + akc);
        float4 b = *(const float4*)(WV + (size_t)(kt + bkr) * 512 + bn + bjc);
        __syncthreads();
        As[akc + 0][ar] = a.x; As[akc + 1][ar] = a.y;
        As[akc + 2][ar] = a.z; As[akc + 3][ar] = a.w;
        *(float4*)&Bs[bkr][bjc] = b;
        __syncthreads();
#pragma unroll
        for (int kk = 0; kk < 16; kk++) {
            float av[4], bv[4];
            *(float4*)av = *(const float4*)&As[kk][ty * 4];
            *(float4*)bv = *(const float4*)&Bs[kk][tx * 4];
#pragma unroll
            for (int i = 0; i < 4; i++)
#pragma unroll
                for (int j = 0; j < 4; j++) acc[i][j] += av[i] * bv[j];
        }
    }
#pragma unroll
    for (int i = 0; i < 4; i++) {
        ushort4 h, l;
        split_bf16(acc[i][0], h.x, l.x); split_bf16(acc[i][1], h.y, l.y);
        split_bf16(acc[i][2], h.z, l.z); split_bf16(acc[i][3], h.w, l.w);
        size_t off = (size_t)z * 512 * 512 + (size_t)(bm + ty * 4 + i) * 512 + bn + tx * 4;
        *(ushort4*)(WavH + off) = h;
        *(ushort4*)(WavL + off) = l;
    }
}

// ================= folded bias =================
__global__ void cvec_kernel(const float* __restrict__ ao_w, const float* __restrict__ ao_b,
                            const float* __restrict__ qkv_b, float* __restrict__ cAll)
{
    int z = blockIdx.x;
    int r = threadIdx.x;
    const float* AO = ao_w + (size_t)z * 512 * 512 + (size_t)r * 512;
    const float* bv = qkv_b + (size_t)z * 1536 + 1024;
    float s = ao_b[z * 512 + r];
    for (int k = 0; k < 512; k++) s += AO[k] * bv[k];
    cAll[z * 512 + r] = s;
}

// ================= prior MLP =================
__global__ void prior_kernel(const float* __restrict__ w1, const float* __restrict__ b1,
                             const float* __restrict__ w2, const float* __restrict__ b2,
                             const float* __restrict__ emb, float* __restrict__ prior)
{
    __shared__ float e[512];
    __shared__ float h1[1024];
    int t = threadIdx.x;
    if (t < 512) e[t] = emb[t];
    __syncthreads();
    float s = b1[t];
    const float* wr = w1 + (size_t)t * 512;
    for (int k = 0; k < 512; k++) s += wr[k] * e[k];
    h1[t] = gelu_exact(s);
    __syncthreads();
    float s2 = b2[t];
    const float* wr2 = w2 + (size_t)t * 1024;
    for (int k = 0; k < 1024; k++) s2 += wr2[k] * h1[k];
    prior[t] = s2;
}

// ================= fp32 -> bf16 hi/lo split =================
__global__ void split_kernel(const float4* __restrict__ src, ushort4* __restrict__ hi,
                             ushort4* __restrict__ lo, int n4)
{
    int i = blockIdx.x * blockDim.x + threadIdx.x;
    if (i >= n4) return;
    float4 v = src[i];
    ushort4 h, l;
    split_bf16(v.x, h.x, l.x); split_bf16(v.y, h.y, l.y);
    split_bf16(v.z, h.z, l.z); split_bf16(v.w, h.w, l.w);
    hi[i] = h;
    lo[i] = l;
}

// ================= final combine =================
__global__ void combine_kernel(const float* __restrict__ img, const float* __restrict__ text,
                               const float* __restrict__ gen, const float* __restrict__ prior,
                               const int* __restrict__ mt, float* __restrict__ out)
{
    int idx = blockIdx.x * blockDim.x + threadIdx.x;
    int bi = idx >> 9;
    int h = idx & 511;
    int m = mt[bi];
    float ei = img[idx];
    if (m == 2) ei = gen[(size_t)BATCH * 512 + idx];
    if (m == 3) ei = prior[h];
    float et = text[idx];
    if (m == 1) et = gen[idx];
    if (m == 3) et = prior[512 + h];
    out[idx] = ei;
    out[(size_t)BATCH * 512 + idx] = et;
}

// ================= host-side pointer resolution + config =================
struct Scratch {
    float *A, *x, *y, *gen, *c, *prior;
    bf16 *imgH, *imgL, *textH, *textL, *xH, *xL, *hH, *hL;
    bf16 *wavH, *wavL, *ipwH, *ipwL, *opwH, *opwL, *f1wH, *f1wL, *f2wH, *f2wL;
};
static Scratch get_scratch() {
    static Scratch s;
    static bool init = false;
    if (!init) {
        cudaGetSymbolAddress((void**)&s.A, d_A);
        cudaGetSymbolAddress((void**)&s.x, d_x);
        cudaGetSymbolAddress((void**)&s.y, d_y);
        cudaGetSymbolAddress((void**)&s.gen, d_gen);
        cudaGetSymbolAddress((void**)&s.c, d_cAll);
        cudaGetSymbolAddress((void**)&s.prior, d_prior);
        cudaGetSymbolAddress((void**)&s.imgH, d_imgH);   cudaGetSymbolAddress((void**)&s.imgL, d_imgL);
        cudaGetSymbolAddress((void**)&s.textH, d_textH); cudaGetSymbolAddress((void**)&s.textL, d_textL);
        cudaGetSymbolAddress((void**)&s.xH, d_xH);       cudaGetSymbolAddress((void**)&s.xL, d_xL);
        cudaGetSymbolAddress((void**)&s.hH, d_hH);       cudaGetSymbolAddress((void**)&s.hL, d_hL);
        cudaGetSymbolAddress((void**)&s.wavH, d_wavH);   cudaGetSymbolAddress((void**)&s.wavL, d_wavL);
        cudaGetSymbolAddress((void**)&s.ipwH, d_ipwH);   cudaGetSymbolAddress((void**)&s.ipwL, d_ipwL);
        cudaGetSymbolAddress((void**)&s.opwH, d_opwH);   cudaGetSymbolAddress((void**)&s.opwL, d_opwL);
        cudaGetSymbolAddress((void**)&s.f1wH, d_f1wH);   cudaGetSymbolAddress((void**)&s.f1wL, d_f1wL);
        cudaGetSymbolAddress((void**)&s.f2wH, d_f2wH);   cudaGetSymbolAddress((void**)&s.f2wL, d_f2wL);
        cudaFuncSetAttribute(mm_gemm<EPI_BIAS>,   cudaFuncAttributeMaxDynamicSharedMemorySize, MM_SMEM);
        cudaFuncSetAttribute(mm_gemm<EPI_GELU>,   cudaFuncAttributeMaxDynamicSharedMemorySize, MM_SMEM);
        cudaFuncSetAttribute(mm_gemm<EPI_ADD>,    cudaFuncAttributeMaxDynamicSharedMemorySize, MM_SMEM);
        cudaFuncSetAttribute(mm_gemm<EPI_RESMIX>, cudaFuncAttributeMaxDynamicSharedMemorySize, MM_SMEM);
        init = true;
    }
    return s;
}

static void run_split(const float* src, bf16* hi, bf16* lo, size_t n) {
    int n4 = (int)(n / 4);
    split_kernel<<<(n4 + 255) / 256, 256>>>((const float4*)src, (ushort4*)hi, (ushort4*)lo, n4);
}

// ================= launch =================
extern "C" void kernel_launch(void* const* d_in, const int* in_sizes, int n_in,
                              void* d_out, int out_size)
{
    const float* img   = (const float*)d_in[0];
    const float* text  = (const float*)d_in[1];
    const float* ipw   = (const float*)d_in[2];
    const float* ipb   = (const float*)d_in[3];
    const float* qkv_w = (const float*)d_in[4];
    const float* qkv_b = (const float*)d_in[5];
    const float* ao_w  = (const float*)d_in[6];
    const float* ao_b  = (const float*)d_in[7];
    const float* ln1g  = (const float*)d_in[8];
    const float* ln1b  = (const float*)d_in[9];
    const float* ln2g  = (const float*)d_in[10];
    const float* ln2b  = (const float*)d_in[11];
    const float* f1w   = (const float*)d_in[12];
    const float* f1b   = (const float*)d_in[13];
    const float* f2w   = (const float*)d_in[14];
    const float* f2b   = (const float*)d_in[15];
    const float* opw   = (const float*)d_in[16];
    const float* opb   = (const float*)d_in[17];
    const float* rw    = (const float*)d_in[18];
    const float* pw1   = (const float*)d_in[19];
    const float* pb1   = (const float*)d_in[20];
    const float* pw2   = (const float*)d_in[21];
    const float* pb2   = (const float*)d_in[22];
    const float* pemb  = (const float*)d_in[23];
    const int*   mt    = (const int*)d_in[24];

    Scratch sc = get_scratch();
    const int M = BATCH;

    // ---- prep: splits, folded attention weights, folded bias, prior ----
    run_split(img,  sc.imgH,  sc.imgL,  (size_t)M * 512);
    run_split(text, sc.textH, sc.textL, (size_t)M * 512);
    run_split(ipw,  sc.ipwH,  sc.ipwL,  (size_t)2 * 512 * 512);
    run_split(opw,  sc.opwH,  sc.opwL,  (size_t)2 * 512 * 512);
    run_split(f1w,  sc.f1wH,  sc.f1wL,  (size_t)6 * 2048 * 512);
    run_split(f2w,  sc.f2wH,  sc.f2wL,  (size_t)6 * 2048 * 512);
    wav_kernel<<<dim3(8, 8, 6), 256>>>(ao_w, qkv_w, sc.wavH, sc.wavL);
    cvec_kernel<<<6, 512>>>(ao_w, ao_b, qkv_b, sc.c);
    prior_kernel<<<1, 1024>>>(pw1, pb1, pw2, pb2, pemb, sc.prior);

    for (int g = 0; g < 2; g++) {
        const float* tgt = (g == 0) ? text : img;
        const bf16* srcH = (g == 0) ? sc.imgH : sc.textH;
        const bf16* srcL = (g == 0) ? sc.imgL : sc.textL;
        const bf16* tgtH = (g == 0) ? sc.textH : sc.imgH;
        const bf16* tgtL = (g == 0) ? sc.textL : sc.imgL;
        size_t gw = (size_t)g;

        // x = src @ ipw^T + ipb
        mm_gemm<EPI_BIAS><<<dim3(4, M / 128), 256, MM_SMEM>>>(
            srcH, srcL, sc.ipwH + gw * 262144, sc.ipwL + gw * 262144,
            ipb + gw * 512, nullptr, nullptr, 0,
            sc.x, nullptr, nullptr, M, 512, 512);

        // A = tgt @ Wav^T + cAll (all 3 layers)
        mm_gemm<EPI_BIAS><<<dim3(12, M / 128), 256, MM_SMEM>>>(
            tgtH, tgtL, sc.wavH + gw * 786432, sc.wavL + gw * 786432,
            sc.c + gw * 1536, nullptr, nullptr, 0,
            sc.A, nullptr, nullptr, M, 1536, 512);

        for (int l = 0; l < 3; l++) {
            size_t zl = gw * 3 + l;
            ln_kernel<<<M, 128>>>(sc.x, sc.A + (size_t)l * 512, 1536,
                                  ln1g + zl * 512, ln1b + zl * 512, sc.x, sc.xH, sc.xL);
            mm_gemm<EPI_GELU><<<dim3(16, M / 128), 256, MM_SMEM>>>(
                sc.xH, sc.xL, sc.f1wH + zl * 1048576, sc.f1wL + zl * 1048576,
                f1b + zl * 2048, nullptr, nullptr, 0,
                nullptr, sc.hH, sc.hL, M, 2048, 512);
            mm_gemm<EPI_ADD><<<dim3(4, M / 128), 256, MM_SMEM>>>(
                sc.hH, sc.hL, sc.f2wH + zl * 1048576, sc.f2wL + zl * 1048576,
                f2b + zl * 512, sc.x, nullptr, 0,
                sc.y, nullptr, nullptr, M, 512, 2048);
            ln_kernel<<<M, 128>>>(sc.y, nullptr, 0,
                                  ln2g + zl * 512, ln2b + zl * 512, sc.x, sc.xH, sc.xL);
        }

        // gen = rw*tgt + (1-rw)*(x @ opw^T + opb)
        mm_gemm<EPI_RESMIX><<<dim3(4, M / 128), 256, MM_SMEM>>>(
            sc.xH, sc.xL, sc.opwH + gw * 262144, sc.opwL + gw * 262144,
            opb + gw * 512, tgt, rw, g,
            sc.gen + gw * (size_t)M * 512, nullptr, nullptr, M, 512, 512);
    }

    combine_kernel<<<(M * 512) / 256, 256>>>(img, text, sc.gen, sc.prior, mt, (float*)d_out);
}

// round 11
// speedup vs baseline: 1.3073x; 1.0896x over previous
#include <cuda_runtime.h>
#include <cuda_bf16.h>
#include <math.h>
#include <stdint.h>

#define BATCH 16384
#define HDIM  512

typedef __nv_bfloat16 bf16;

// ================= portable PTX helpers (sm_80+ ISA only) =================
__device__ __forceinline__ uint32_t smem_u32(const void* p) {
    uint32_t a;
    asm("{ .reg .u64 t; cvta.to.shared.u64 t, %1; cvt.u32.u64 %0, t; }" : "=r"(a) : "l"(p));
    return a;
}
#define CP_ASYNC16(dst, src) \
    asm volatile("cp.async.cg.shared.global [%0], [%1], 16;" :: "r"(dst), "l"(src) : "memory")
#define CP_COMMIT() asm volatile("cp.async.commit_group;" ::: "memory")
#define CP_WAIT(n)  asm volatile("cp.async.wait_group %0;" :: "n"(n) : "memory")
#define LDMATRIX_X4(r0, r1, r2, r3, addr) \
    asm volatile("ldmatrix.sync.aligned.m8n8.x4.shared.b16 {%0,%1,%2,%3}, [%4];" \
        : "=r"(r0), "=r"(r1), "=r"(r2), "=r"(r3) : "r"(addr))
#define MMA16816(c0, c1, c2, c3, a0, a1, a2, a3, b0, b1) \
    asm volatile("mma.sync.aligned.m16n8k16.row.col.f32.bf16.bf16.f32 " \
        "{%0,%1,%2,%3}, {%4,%5,%6,%7}, {%8,%9}, {%0,%1,%2,%3};" \
        : "+f"(c0), "+f"(c1), "+f"(c2), "+f"(c3) \
        : "r"(a0), "r"(a1), "r"(a2), "r"(a3), "r"(b0), "r"(b1))

__device__ __forceinline__ uint32_t sw128(uint32_t off) { return off ^ ((off >> 3) & 0x70); }

// ================= scratch (static __device__) =================
__device__ float d_A[2][(size_t)BATCH * 1536];
__device__ float d_x[2][(size_t)BATCH * 512];
__device__ float d_y[2][(size_t)BATCH * 512];
__device__ float d_gen[2][(size_t)BATCH * 512];
__device__ float d_cAll[2 * 1536];
__device__ float d_prior[1024];

__device__ bf16 d_imgH[(size_t)BATCH * 512],  d_imgL[(size_t)BATCH * 512];
__device__ bf16 d_textH[(size_t)BATCH * 512], d_textL[(size_t)BATCH * 512];
__device__ bf16 d_xH[2][(size_t)BATCH * 512], d_xL[2][(size_t)BATCH * 512];
__device__ bf16 d_hH[2][(size_t)BATCH * 2048], d_hL[2][(size_t)BATCH * 2048];
__device__ bf16 d_wavH[6 * 512 * 512],        d_wavL[6 * 512 * 512];
__device__ bf16 d_ipwH[2 * 512 * 512],        d_ipwL[2 * 512 * 512];
__device__ bf16 d_opwH[2 * 512 * 512],        d_opwL[2 * 512 * 512];
__device__ bf16 d_f1wH[(size_t)6 * 2048 * 512], d_f1wL[(size_t)6 * 2048 * 512];
__device__ bf16 d_f2wH[(size_t)6 * 2048 * 512], d_f2wL[(size_t)6 * 2048 * 512];

__device__ __forceinline__ float gelu_exact(float x) {
    return 0.5f * x * (1.0f + erff(x * 0.70710678118654752440f));
}
__device__ __forceinline__ void split_bf16(float v, unsigned short& h, unsigned short& l) {
    __nv_bfloat16 hb = __float2bfloat16_rn(v);
    float hf = __bfloat162float(hb);
    __nv_bfloat16 lb = __float2bfloat16_rn(v - hf);
    h = __bfloat16_as_ushort(hb);
    l = __bfloat16_as_ushort(lb);
}

// ================= z-batched mma.sync bf16 GEMM =================
// C = epi(A @ W^T + bias), fp32 via 3-term bf16 split: AhBh + AhBl + AlBh.
// Pass 1 (nk iters): stage holds {Ah, Bh, Bl}; one A tile feeds MMAs against
// BOTH B planes (A L2 traffic and barrier count cut by a third vs 3-pass).
// Pass 2 (nk iters): stage holds {Al, Bh}. CTA tile 128x128, 8 warps 64x32,
// 2-stage double buffer (R7-proven ordering). blockIdx.z selects generator.
enum { EPI_BIAS = 0, EPI_GELU = 1, EPI_ADD = 2, EPI_RESMIX = 3 };

struct ZOps {
    const bf16 *Ahi, *Alo, *Bhi, *Blo;
    const float *bias, *aux;
    float *Cf; bf16 *Chi, *Clo;
};

#define STAGES 2
#define TILE_BYTES 16384            // 128 rows x 128 bytes
#define STAGE_BYTES (3 * TILE_BYTES)
#define MM_SMEM (STAGES * STAGE_BYTES)   // 96 KB

template <int EPI>
__global__ __launch_bounds__(256, 2) void mm_gemm(
    ZOps z0, ZOps z1, const float* __restrict__ rwp, int M, int N, int K)
{
    extern __shared__ char smem[];
    const uint32_t sb = smem_u32(smem);
    const ZOps P = (blockIdx.z == 0) ? z0 : z1;
    const int tid = threadIdx.x;
    const int wid = tid >> 5, lane = tid & 31;
    const int warp_m = wid >> 2;          // 0..1 -> 64-row half
    const int warp_n = wid & 3;           // 0..3 -> 32-col quarter
    const int bm = blockIdx.y * 128, bn = blockIdx.x * 128;
    const int nk = K >> 6;
    const int nIter = 2 * nk;

    const size_t rowPitch = (size_t)K * 2;

    auto load_tile = [&](int s, int t) {
        uint32_t sA  = sb + s * STAGE_BYTES;
        uint32_t sB0 = sA + TILE_BYTES;
        uint32_t sB1 = sB0 + TILE_BYTES;
        if (t < nk) {
            const char* gA  = (const char*)(P.Ahi + (size_t)bm * K) + (size_t)t * 128;
            const char* gB0 = (const char*)(P.Bhi + (size_t)bn * K) + (size_t)t * 128;
            const char* gB1 = (const char*)(P.Blo + (size_t)bn * K) + (size_t)t * 128;
#pragma unroll
            for (int i = 0; i < 4; i++) {
                int id = i * 256 + tid;
                int row = id >> 3, u = id & 7;
                uint32_t so = sw128((uint32_t)(row * 128 + u * 16));
                size_t go = (size_t)row * rowPitch + u * 16;
                CP_ASYNC16(sA + so,  gA + go);
                CP_ASYNC16(sB0 + so, gB0 + go);
                CP_ASYNC16(sB1 + so, gB1 + go);
            }
        } else {
            int tt = t - nk;
            const char* gA  = (const char*)(P.Alo + (size_t)bm * K) + (size_t)tt * 128;
            const char* gB0 = (const char*)(P.Bhi + (size_t)bn * K) + (size_t)tt * 128;
#pragma unroll
            for (int i = 0; i < 4; i++) {
                int id = i * 256 + tid;
                int row = id >> 3, u = id & 7;
                uint32_t so = sw128((uint32_t)(row * 128 + u * 16));
                size_t go = (size_t)row * rowPitch + u * 16;
                CP_ASYNC16(sA + so,  gA + go);
                CP_ASYNC16(sB0 + so, gB0 + go);
            }
        }
    };

    float acc[4][4][4];
#pragma unroll
    for (int i = 0; i < 4; i++)
#pragma unroll
        for (int j = 0; j < 4; j++)
#pragma unroll
            for (int e = 0; e < 4; e++) acc[i][j][e] = 0.0f;

    const int g = lane >> 3, lr = lane & 7;
    const int arow = warp_m * 64 + (g & 1) * 8 + lr;   // A frag rows
    const int akb  = (g >> 1) * 16;
    const int brow = warp_n * 32 + (g >> 1) * 8 + lr;  // B frag rows
    const int bkb  = (g & 1) * 16;

    load_tile(0, 0); CP_COMMIT();

    for (int kt = 0; kt < nIter; kt++) {
        if (kt + 1 < nIter) {
            load_tile((kt + 1) & 1, kt + 1);
            CP_COMMIT();
            CP_WAIT(1);
        } else {
            CP_WAIT(0);
        }
        __syncthreads();

        const bool dual = (kt < nk);
        uint32_t sA  = sb + (kt & 1) * STAGE_BYTES;
        uint32_t sB0 = sA + TILE_BYTES;
        uint32_t sB1 = sB0 + TILE_BYTES;
#pragma unroll
        for (int ki = 0; ki < 4; ki++) {
            uint32_t a[4][4];
#pragma unroll
            for (int mt = 0; mt < 4; mt++) {
                uint32_t addr = sA + sw128((uint32_t)((arow + mt * 16) * 128 + ki * 32 + akb));
                LDMATRIX_X4(a[mt][0], a[mt][1], a[mt][2], a[mt][3], addr);
            }
            uint32_t b[4][2];
#pragma unroll
            for (int p = 0; p < 2; p++) {
                uint32_t addr = sB0 + sw128((uint32_t)((brow + p * 16) * 128 + ki * 32 + bkb));
                uint32_t r0, r1, r2, r3;
                LDMATRIX_X4(r0, r1, r2, r3, addr);
                b[2 * p][0] = r0;     b[2 * p][1] = r1;
                b[2 * p + 1][0] = r2; b[2 * p + 1][1] = r3;
            }
#pragma unroll
            for (int mt = 0; mt < 4; mt++)
#pragma unroll
                for (int nt = 0; nt < 4; nt++)
                    MMA16816(acc[mt][nt][0], acc[mt][nt][1], acc[mt][nt][2], acc[mt][nt][3],
                             a[mt][0], a[mt][1], a[mt][2], a[mt][3],
                             b[nt][0], b[nt][1]);
            if (dual) {
#pragma unroll
                for (int p = 0; p < 2; p++) {
                    uint32_t addr = sB1 + sw128((uint32_t)((brow + p * 16) * 128 + ki * 32 + bkb));
                    uint32_t r0, r1, r2, r3;
                    LDMATRIX_X4(r0, r1, r2, r3, addr);
                    b[2 * p][0] = r0;     b[2 * p][1] = r1;
                    b[2 * p + 1][0] = r2; b[2 * p + 1][1] = r3;
                }
#pragma unroll
                for (int mt = 0; mt < 4; mt++)
#pragma unroll
                    for (int nt = 0; nt < 4; nt++)
                        MMA16816(acc[mt][nt][0], acc[mt][nt][1], acc[mt][nt][2], acc[mt][nt][3],
                                 a[mt][0], a[mt][1], a[mt][2], a[mt][3],
                                 b[nt][0], b[nt][1]);
            }
        }
        __syncthreads();
    }

    // ---- fused epilogue straight from fragments ----
    float rwv = 0.0f, rwc = 0.0f;
    if (EPI == EPI_RESMIX) { rwv = rwp[blockIdx.z]; rwc = 1.0f - rwv; }
    const int qr = lane >> 2, qc = (lane & 3) * 2;

#pragma unroll
    for (int mt = 0; mt < 4; mt++) {
#pragma unroll
        for (int nt = 0; nt < 4; nt++) {
            int n = bn + warp_n * 32 + nt * 8 + qc;
            float2 b2 = *(const float2*)(P.bias + n);
#pragma unroll
            for (int h = 0; h < 2; h++) {
                int m = bm + warp_m * 64 + mt * 16 + qr + h * 8;
                float v0 = acc[mt][nt][2 * h + 0] + b2.x;
                float v1 = acc[mt][nt][2 * h + 1] + b2.y;
                size_t gr = (size_t)m * N + n;
                if (EPI == EPI_GELU) { v0 = gelu_exact(v0); v1 = gelu_exact(v1); }
                if (EPI == EPI_ADD) {
                    float2 a2 = *(const float2*)(P.aux + gr);
                    v0 += a2.x; v1 += a2.y;
                }
                if (EPI == EPI_RESMIX) {
                    float2 a2 = *(const float2*)(P.aux + gr);
                    v0 = rwv * a2.x + rwc * v0;
                    v1 = rwv * a2.y + rwc * v1;
                }
                if (P.Cf) *(float2*)(P.Cf + gr) = make_float2(v0, v1);
                if (P.Chi) {
                    ushort2 hh, ll;
                    split_bf16(v0, hh.x, ll.x);
                    split_bf16(v1, hh.y, ll.y);
                    *(ushort2*)(P.Chi + gr) = hh;
                    *(ushort2*)(P.Clo + gr) = ll;
                }
            }
        }
    }
}

// ================= z-batched LayerNorm (fp32 out + bf16 hi/lo planes) ========
struct ZLn {
    const float *x, *add, *gg, *bb;
    float *out; bf16 *oh, *ol;
};

__global__ void ln_kernel(ZLn a0, ZLn a1, int addStride)
{
    __shared__ float red[4];
    const ZLn P = (blockIdx.y == 0) ? a0 : a1;
    int row = blockIdx.x;
    int t = threadIdx.x;

    float4 v = ((const float4*)(P.x + (size_t)row * 512))[t];
    if (P.add) {
        float4 a = ((const float4*)(P.add + (size_t)row * addStride))[t];
        v.x += a.x; v.y += a.y; v.z += a.z; v.w += a.w;
    }
    float s = v.x + v.y + v.z + v.w;
#pragma unroll
    for (int o = 16; o; o >>= 1) s += __shfl_xor_sync(0xffffffff, s, o);
    if ((t & 31) == 0) red[t >> 5] = s;
    __syncthreads();
    float mean = (red[0] + red[1] + red[2] + red[3]) * (1.0f / 512.0f);

    float dx0 = v.x - mean, dx1 = v.y - mean, dx2 = v.z - mean, dx3 = v.w - mean;
    float q = dx0 * dx0 + dx1 * dx1 + dx2 * dx2 + dx3 * dx3;
#pragma unroll
    for (int o = 16; o; o >>= 1) q += __shfl_xor_sync(0xffffffff, q, o);
    __syncthreads();
    if ((t & 31) == 0) red[t >> 5] = q;
    __syncthreads();
    float var = (red[0] + red[1] + red[2] + red[3]) * (1.0f / 512.0f);
    float inv = rsqrtf(var + 1e-5f);

    float4 gv = ((const float4*)P.gg)[t];
    float4 bv = ((const float4*)P.bb)[t];
    float4 o4;
    o4.x = dx0 * inv * gv.x + bv.x;
    o4.y = dx1 * inv * gv.y + bv.y;
    o4.z = dx2 * inv * gv.z + bv.z;
    o4.w = dx3 * inv * gv.w + bv.w;
    ((float4*)(P.out + (size_t)row * 512))[t] = o4;

    ushort4 h, l;
    split_bf16(o4.x, h.x, l.x); split_bf16(o4.y, h.y, l.y);
    split_bf16(o4.z, h.z, l.z); split_bf16(o4.w, h.w, l.w);
    *(ushort4*)(P.oh + (size_t)row * 512 + t * 4) = h;
    *(ushort4*)(P.ol + (size_t)row * 512 + t * 4) = l;
}

// ================= Wav prep: Wav[z] = ao_w[z] @ wv[z] -> bf16 planes =========
__global__ __launch_bounds__(256) void wav_kernel(const float* __restrict__ ao_w,
                                                  const float* __restrict__ qkv_w,
                                                  bf16* __restrict__ WavH, bf16* __restrict__ WavL)
{
    __shared__ float As[16][64];
    __shared__ float Bs[16][64];
    int z = blockIdx.z;
    const float* AO = ao_w + (size_t)z * 512 * 512;
    const float* WV = qkv_w + (size_t)z * 1536 * 512 + (size_t)1024 * 512;
    int tid = threadIdx.x, tx = tid & 15, ty = tid >> 4;
    int bm = blockIdx.y * 64, bn = blockIdx.x * 64;
    int ar = tid >> 2, akc = (tid & 3) * 4;
    int bkr = tid >> 4, bjc = (tid & 15) * 4;

    float acc[4][4];
#pragma unroll
    for (int i = 0; i < 4; i++)
#pragma unroll
        for (int j = 0; j < 4; j++) acc[i][j] = 0.0f;

    for (int kt = 0; kt < 512; kt += 16) {
        float4 a = *(const float4*)(AO + (size_t)(bm + ar) * 512 + kt + akc);
        float4 b = *(const float4*)(WV + (size_t)(kt + bkr) * 512 + bn + bjc);
        __syncthreads();
        As[akc + 0][ar] = a.x; As[akc + 1][ar] = a.y;
        As[akc + 2][ar] = a.z; As[akc + 3][ar] = a.w;
        *(float4*)&Bs[bkr][bjc] = b;
        __syncthreads();
#pragma unroll
        for (int kk = 0; kk < 16; kk++) {
            float av[4], bv[4];
            *(float4*)av = *(const float4*)&As[kk][ty * 4];
            *(float4*)bv = *(const float4*)&Bs[kk][tx * 4];
#pragma unroll
            for (int i = 0; i < 4; i++)
#pragma unroll
                for (int j = 0; j < 4; j++) acc[i][j] += av[i] * bv[j];
        }
    }
#pragma unroll
    for (int i = 0; i < 4; i++) {
        ushort4 h, l;
        split_bf16(acc[i][0], h.x, l.x); split_bf16(acc[i][1], h.y, l.y);
        split_bf16(acc[i][2], h.z, l.z); split_bf16(acc[i][3], h.w, l.w);
        size_t off = (size_t)z * 512 * 512 + (size_t)(bm + ty * 4 + i) * 512 + bn + tx * 4;
        *(ushort4*)(WavH + off) = h;
        *(ushort4*)(WavL + off) = l;
    }
}

// ================= folded bias =================
__global__ void cvec_kernel(const float* __restrict__ ao_w, const float* __restrict__ ao_b,
                            const float* __restrict__ qkv_b, float* __restrict__ cAll)
{
    int z = blockIdx.x;
    int r = threadIdx.x;
    const float* AO = ao_w + (size_t)z * 512 * 512 + (size_t)r * 512;
    const float* bv = qkv_b + (size_t)z * 1536 + 1024;
    float s = ao_b[z * 512 + r];
    for (int k = 0; k < 512; k++) s += AO[k] * bv[k];
    cAll[z * 512 + r] = s;
}

// ================= prior MLP =================
__global__ void prior_kernel(const float* __restrict__ w1, const float* __restrict__ b1,
                             const float* __restrict__ w2, const float* __restrict__ b2,
                             const float* __restrict__ emb, float* __restrict__ prior)
{
    __shared__ float e[512];
    __shared__ float h1[1024];
    int t = threadIdx.x;
    if (t < 512) e[t] = emb[t];
    __syncthreads();
    float s = b1[t];
    const float* wr = w1 + (size_t)t * 512;
    for (int k = 0; k < 512; k++) s += wr[k] * e[k];
    h1[t] = gelu_exact(s);
    __syncthreads();
    float s2 = b2[t];
    const float* wr2 = w2 + (size_t)t * 1024;
    for (int k = 0; k < 1024; k++) s2 += wr2[k] * h1[k];
    prior[t] = s2;
}

// ================= fp32 -> bf16 hi/lo split =================
__global__ void split_kernel(const float4* __restrict__ src, ushort4* __restrict__ hi,
                             ushort4* __restrict__ lo, int n4)
{
    int i = blockIdx.x * blockDim.x + threadIdx.x;
    if (i >= n4) return;
    float4 v = src[i];
    ushort4 h, l;
    split_bf16(v.x, h.x, l.x); split_bf16(v.y, h.y, l.y);
    split_bf16(v.z, h.z, l.z); split_bf16(v.w, h.w, l.w);
    hi[i] = h;
    lo[i] = l;
}

// ================= final combine =================
__global__ void combine_kernel(const float* __restrict__ img, const float* __restrict__ text,
                               const float* __restrict__ gen0, const float* __restrict__ gen1,
                               const float* __restrict__ prior,
                               const int* __restrict__ mt, float* __restrict__ out)
{
    int idx = blockIdx.x * blockDim.x + threadIdx.x;
    int bi = idx >> 9;
    int h = idx & 511;
    int m = mt[bi];
    float ei = img[idx];
    if (m == 2) ei = gen1[idx];
    if (m == 3) ei = prior[h];
    float et = text[idx];
    if (m == 1) et = gen0[idx];
    if (m == 3) et = prior[512 + h];
    out[idx] = ei;
    out[(size_t)BATCH * 512 + idx] = et;
}

// ================= host-side pointer resolution + config =================
struct Scratch {
    float *A[2], *x[2], *y[2], *gen[2], *c, *prior;
    bf16 *imgH, *imgL, *textH, *textL;
    bf16 *xH[2], *xL[2], *hH[2], *hL[2];
    bf16 *wavH, *wavL, *ipwH, *ipwL, *opwH, *opwL, *f1wH, *f1wL, *f2wH, *f2wL;
};
static Scratch get_scratch() {
    static Scratch s;
    static bool init = false;
    if (!init) {
        float* p;
        cudaGetSymbolAddress((void**)&p, d_A);    s.A[0] = p; s.A[1] = p + (size_t)BATCH * 1536;
        cudaGetSymbolAddress((void**)&p, d_x);    s.x[0] = p; s.x[1] = p + (size_t)BATCH * 512;
        cudaGetSymbolAddress((void**)&p, d_y);    s.y[0] = p; s.y[1] = p + (size_t)BATCH * 512;
        cudaGetSymbolAddress((void**)&p, d_gen);  s.gen[0] = p; s.gen[1] = p + (size_t)BATCH * 512;
        cudaGetSymbolAddress((void**)&s.c, d_cAll);
        cudaGetSymbolAddress((void**)&s.prior, d_prior);
        bf16* q;
        cudaGetSymbolAddress((void**)&s.imgH, d_imgH);   cudaGetSymbolAddress((void**)&s.imgL, d_imgL);
        cudaGetSymbolAddress((void**)&s.textH, d_textH); cudaGetSymbolAddress((void**)&s.textL, d_textL);
        cudaGetSymbolAddress((void**)&q, d_xH);   s.xH[0] = q; s.xH[1] = q + (size_t)BATCH * 512;
        cudaGetSymbolAddress((void**)&q, d_xL);   s.xL[0] = q; s.xL[1] = q + (size_t)BATCH * 512;
        cudaGetSymbolAddress((void**)&q, d_hH);   s.hH[0] = q; s.hH[1] = q + (size_t)BATCH * 2048;
        cudaGetSymbolAddress((void**)&q, d_hL);   s.hL[0] = q; s.hL[1] = q + (size_t)BATCH * 2048;
        cudaGetSymbolAddress((void**)&s.wavH, d_wavH);   cudaGetSymbolAddress((void**)&s.wavL, d_wavL);
        cudaGetSymbolAddress((void**)&s.ipwH, d_ipwH);   cudaGetSymbolAddress((void**)&s.ipwL, d_ipwL);
        cudaGetSymbolAddress((void**)&s.opwH, d_opwH);   cudaGetSymbolAddress((void**)&s.opwL, d_opwL);
        cudaGetSymbolAddress((void**)&s.f1wH, d_f1wH);   cudaGetSymbolAddress((void**)&s.f1wL, d_f1wL);
        cudaGetSymbolAddress((void**)&s.f2wH, d_f2wH);   cudaGetSymbolAddress((void**)&s.f2wL, d_f2wL);
        cudaFuncSetAttribute(mm_gemm<EPI_BIAS>,   cudaFuncAttributeMaxDynamicSharedMemorySize, MM_SMEM);
        cudaFuncSetAttribute(mm_gemm<EPI_GELU>,   cudaFuncAttributeMaxDynamicSharedMemorySize, MM_SMEM);
        cudaFuncSetAttribute(mm_gemm<EPI_ADD>,    cudaFuncAttributeMaxDynamicSharedMemorySize, MM_SMEM);
        cudaFuncSetAttribute(mm_gemm<EPI_RESMIX>, cudaFuncAttributeMaxDynamicSharedMemorySize, MM_SMEM);
        init = true;
    }
    return s;
}

static void run_split(const float* src, bf16* hi, bf16* lo, size_t n) {
    int n4 = (int)(n / 4);
    split_kernel<<<(n4 + 255) / 256, 256>>>((const float4*)src, (ushort4*)hi, (ushort4*)lo, n4);
}

// ================= launch =================
extern "C" void kernel_launch(void* const* d_in, const int* in_sizes, int n_in,
                              void* d_out, int out_size)
{
    const float* img   = (const float*)d_in[0];
    const float* text  = (const float*)d_in[1];
    const float* ipw   = (const float*)d_in[2];
    const float* ipb   = (const float*)d_in[3];
    const float* qkv_w = (const float*)d_in[4];
    const float* qkv_b = (const float*)d_in[5];
    const float* ao_w  = (const float*)d_in[6];
    const float* ao_b  = (const float*)d_in[7];
    const float* ln1g  = (const float*)d_in[8];
    const float* ln1b  = (const float*)d_in[9];
    const float* ln2g  = (const float*)d_in[10];
    const float* ln2b  = (const float*)d_in[11];
    const float* f1w   = (const float*)d_in[12];
    const float* f1b   = (const float*)d_in[13];
    const float* f2w   = (const float*)d_in[14];
    const float* f2b   = (const float*)d_in[15];
    const float* opw   = (const float*)d_in[16];
    const float* opb   = (const float*)d_in[17];
    const float* rw    = (const float*)d_in[18];
    const float* pw1   = (const float*)d_in[19];
    const float* pb1   = (const float*)d_in[20];
    const float* pw2   = (const float*)d_in[21];
    const float* pb2   = (const float*)d_in[22];
    const float* pemb  = (const float*)d_in[23];
    const int*   mt    = (const int*)d_in[24];

    Scratch sc = get_scratch();
    const int M = BATCH;

    // ---- prep: splits, folded attention weights, folded bias, prior ----
    run_split(img,  sc.imgH,  sc.imgL,  (size_t)M * 512);
    run_split(text, sc.textH, sc.textL, (size_t)M * 512);
    run_split(ipw,  sc.ipwH,  sc.ipwL,  (size_t)2 * 512 * 512);
    run_split(opw,  sc.opwH,  sc.opwL,  (size_t)2 * 512 * 512);
    run_split(f1w,  sc.f1wH,  sc.f1wL,  (size_t)6 * 2048 * 512);
    run_split(f2w,  sc.f2wH,  sc.f2wL,  (size_t)6 * 2048 * 512);
    wav_kernel<<<dim3(8, 8, 6), 256>>>(ao_w, qkv_w, sc.wavH, sc.wavL);
    cvec_kernel<<<6, 512>>>(ao_w, ao_b, qkv_b, sc.c);
    prior_kernel<<<1, 1024>>>(pw1, pb1, pw2, pb2, pemb, sc.prior);

    // per-generator source/target planes: g0 src=img tgt=text; g1 src=text tgt=img
    const bf16* srcH[2] = { sc.imgH,  sc.textH };
    const bf16* srcL[2] = { sc.imgL,  sc.textL };
    const bf16* tgtH[2] = { sc.textH, sc.imgH };
    const bf16* tgtL[2] = { sc.textL, sc.imgL };
    const float* tgtF[2] = { text, img };

    auto zo = [](const bf16* ah, const bf16* al, const bf16* bh, const bf16* bl,
                 const float* bias, const float* aux,
                 float* cf, bf16* chi, bf16* clo) {
        ZOps z; z.Ahi = ah; z.Alo = al; z.Bhi = bh; z.Blo = bl;
        z.bias = bias; z.aux = aux; z.Cf = cf; z.Chi = chi; z.Clo = clo;
        return z;
    };

    // x = src @ ipw^T + ipb          (both generators, one launch)
    mm_gemm<EPI_BIAS><<<dim3(4, M / 128, 2), 256, MM_SMEM>>>(
        zo(srcH[0], srcL[0], sc.ipwH, sc.ipwL, ipb, nullptr, sc.x[0], nullptr, nullptr),
        zo(srcH[1], srcL[1], sc.ipwH + 262144, sc.ipwL + 262144, ipb + 512, nullptr, sc.x[1], nullptr, nullptr),
        nullptr, M, 512, 512);

    // A = tgt @ Wav^T + cAll (all 3 layers, both generators)
    mm_gemm<EPI_BIAS><<<dim3(12, M / 128, 2), 256, MM_SMEM>>>(
        zo(tgtH[0], tgtL[0], sc.wavH, sc.wavL, sc.c, nullptr, sc.A[0], nullptr, nullptr),
        zo(tgtH[1], tgtL[1], sc.wavH + 786432, sc.wavL + 786432, sc.c + 1536, nullptr, sc.A[1], nullptr, nullptr),
        nullptr, M, 1536, 512);

    for (int l = 0; l < 3; l++) {
        size_t z0 = (size_t)l;          // g=0 layer index
        size_t z1 = (size_t)(3 + l);    // g=1 layer index

        // x = LN1(x + A[:, l])
        {
            ZLn a0 = { sc.x[0], sc.A[0] + (size_t)l * 512, ln1g + z0 * 512, ln1b + z0 * 512,
                       sc.x[0], sc.xH[0], sc.xL[0] };
            ZLn a1 = { sc.x[1], sc.A[1] + (size_t)l * 512, ln1g + z1 * 512, ln1b + z1 * 512,
                       sc.x[1], sc.xH[1], sc.xL[1] };
            ln_kernel<<<dim3(M, 2), 128>>>(a0, a1, 1536);
        }
        // h = gelu(x @ f1w^T + f1b)
        mm_gemm<EPI_GELU><<<dim3(16, M / 128, 2), 256, MM_SMEM>>>(
            zo(sc.xH[0], sc.xL[0], sc.f1wH + z0 * 1048576, sc.f1wL + z0 * 1048576,
               f1b + z0 * 2048, nullptr, nullptr, sc.hH[0], sc.hL[0]),
            zo(sc.xH[1], sc.xL[1], sc.f1wH + z1 * 1048576, sc.f1wL + z1 * 1048576,
               f1b + z1 * 2048, nullptr, nullptr, sc.hH[1], sc.hL[1]),
            nullptr, M, 2048, 512);
        // y = x + h @ f2w^T + f2b
        mm_gemm<EPI_ADD><<<dim3(4, M / 128, 2), 256, MM_SMEM>>>(
            zo(sc.hH[0], sc.hL[0], sc.f2wH + z0 * 1048576, sc.f2wL + z0 * 1048576,
               f2b + z0 * 512, sc.x[0], sc.y[0], nullptr, nullptr),
            zo(sc.hH[1], sc.hL[1], sc.f2wH + z1 * 1048576, sc.f2wL + z1 * 1048576,
               f2b + z1 * 512, sc.x[1], sc.y[1], nullptr, nullptr),
            nullptr, M, 512, 2048);
        // x = LN2(y)
        {
            ZLn a0 = { sc.y[0], nullptr, ln2g + z0 * 512, ln2b + z0 * 512,
                       sc.x[0], sc.xH[0], sc.xL[0] };
            ZLn a1 = { sc.y[1], nullptr, ln2g + z1 * 512, ln2b + z1 * 512,
                       sc.x[1], sc.xH[1], sc.xL[1] };
            ln_kernel<<<dim3(M, 2), 128>>>(a0, a1, 0);
        }
    }

    // gen = rw*tgt + (1-rw)*(x @ opw^T + opb)
    mm_gemm<EPI_RESMIX><<<dim3(4, M / 128, 2), 256, MM_SMEM>>>(
        zo(sc.xH[0], sc.xL[0], sc.opwH, sc.opwL, opb, tgtF[0], sc.gen[0], nullptr, nullptr),
        zo(sc.xH[1], sc.xL[1], sc.opwH + 262144, sc.opwL + 262144, opb + 512, tgtF[1], sc.gen[1], nullptr, nullptr),
        rw, M, 512, 512);

    combine_kernel<<<(M * 512) / 256, 256>>>(img, text, sc.gen[0], sc.gen[1], sc.prior, mt, (float*)d_out);
}